// round 6
// baseline (speedup 1.0000x reference)
#include <cuda_runtime.h>

#define BB 128
#define NN 512
#define CC 7
#define HH 64
#define KK 16
#define EPSF 1e-5f

typedef unsigned long long ull;

// ---------------- scratch (device globals: allocation-free) ----------------
__device__ __align__(16) float g_hA[BB*NN*HH];      // 16.8 MB
__device__ __align__(16) float g_hB[BB*NN*HH];      // 16.8 MB
__device__ __align__(16) float g_ac[BB*NN*2*HH];    // 33.5 MB  [point][0:64]=a, [64:128]=c
__device__ float g_sq[BB*NN];
__device__ int   g_idx[BB*NN*KK];
__device__ float g_wfT[2*HH*128];                   // folded weights, [r][hh][o] (transposed)
__device__ float g_wb[2*HH];                        // folded bias

// ---------------- packed fp32x2 helpers (Blackwell f32x2 pipe) -------------
__device__ __forceinline__ ull fma2(ull a, ull b, ull c){
    ull d; asm("fma.rn.f32x2 %0, %1, %2, %3;" : "=l"(d) : "l"(a), "l"(b), "l"(c)); return d;
}
__device__ __forceinline__ ull add2(ull a, ull b){
    ull d; asm("add.rn.f32x2 %0, %1, %2;" : "=l"(d) : "l"(a), "l"(b)); return d;
}
__device__ __forceinline__ float lo2(ull a){ return __uint_as_float((unsigned)a); }
__device__ __forceinline__ float hi2(ull a){ return __uint_as_float((unsigned)(a >> 32)); }
__device__ __forceinline__ ull pk2(float lo, float hi){
    ull d; asm("mov.b64 %0, {%1,%2};" : "=l"(d) : "f"(lo), "f"(hi)); return d;
}

// ---------------------------------------------------------------------------
// k_prep: fold BN scale into edgeconv weights, TRANSPOSED layout [r][hh][o]
// ---------------------------------------------------------------------------
__global__ void k_prep(const float* __restrict__ wnb,
                       const float* __restrict__ gnb,
                       const float* __restrict__ bnb)
{
    int i = blockIdx.x*256 + threadIdx.x;
    if (i < 2*HH) g_wb[i] = bnb[i];
    if (i >= 2*HH*128) return;
    int r   = i >> 13;
    int rem = i & 8191;
    int hh  = rem >> 7;
    int o   = rem & 127;
    float inv = rsqrtf(1.0f + EPSF);
    float v;
    if (o < HH){
        float s = gnb[r*HH + o] * inv;
        v = (wnb[(r*HH + o)*128 + hh] - wnb[(r*HH + o)*128 + 64 + hh]) * s;
    } else {
        int oo = o - HH;
        float s = gnb[r*HH + oo] * inv;
        v = wnb[(r*HH + oo)*128 + 64 + hh] * s;
    }
    g_wfT[i] = v;
}

// ---------------------------------------------------------------------------
// k_input: h = relu(bn2(W2 relu(bn1(W1 x)))), fused row-norm (g_sq).
// ---------------------------------------------------------------------------
__global__ void k_input(const float* __restrict__ x,
                        const float* __restrict__ w1, const float* __restrict__ g1,
                        const float* __restrict__ b1,
                        const float* __restrict__ w2, const float* __restrict__ g2,
                        const float* __restrict__ b2)
{
    __shared__ float w1s[HH*CC];
    __shared__ float w2sT[HH][HH];
    __shared__ float xs[16][CC];
    __shared__ __align__(16) float h1s[16][HH];
    __shared__ float part[32];
    int tx = threadIdx.x, ty = threadIdx.y;
    int tid = ty*64 + tx;
    int p0 = blockIdx.x*16;
    int b  = p0 / NN;
    int n0 = p0 % NN;

    for (int i = tid; i < HH*CC; i += 1024) w1s[i] = w1[i];
    for (int i = tid; i < HH*HH; i += 1024) { int o = i>>6, hh = i&63; w2sT[hh][o] = w2[i]; }
    if (tid < 16*CC) { int c = tid/16, i = tid%16; xs[i][c] = x[b*CC*NN + c*NN + n0 + i]; }
    __syncthreads();

    float inv = rsqrtf(1.0f + EPSF);
    float s1 = g1[tx]*inv, bb1 = b1[tx];
    float s2 = g2[tx]*inv, bb2 = b2[tx];

    {
        float acc = 0.f;
        #pragma unroll
        for (int c = 0; c < CC; c++) acc = fmaf(w1s[tx*CC + c], xs[ty][c], acc);
        h1s[ty][tx] = fmaxf(acc*s1 + bb1, 0.f);
    }
    __syncthreads();
    float val;
    {
        float a0=0,a1=0,a2=0,a3=0;
        const float4* hp = reinterpret_cast<const float4*>(h1s[ty]);
        #pragma unroll
        for (int q = 0; q < 16; q++){
            float4 v = hp[q];
            int hh = q*4;
            a0 = fmaf(w2sT[hh+0][tx], v.x, a0);
            a1 = fmaf(w2sT[hh+1][tx], v.y, a1);
            a2 = fmaf(w2sT[hh+2][tx], v.z, a2);
            a3 = fmaf(w2sT[hh+3][tx], v.w, a3);
        }
        val = fmaxf(((a0+a1)+(a2+a3))*s2 + bb2, 0.f);
        g_hA[(p0+ty)*HH + tx] = val;
    }
    float ss = val*val;
    #pragma unroll
    for (int off = 16; off; off >>= 1) ss += __shfl_down_sync(0xffffffffu, ss, off);
    if ((tx & 31) == 0) part[tid >> 5] = ss;
    __syncthreads();
    if (tx == 0) g_sq[p0 + ty] = part[2*ty] + part[2*ty + 1];
}

// ---------------------------------------------------------------------------
// kNN v2: 128 queries/block (grid 4x128=512 blocks), 2 candidates per inner
// iteration with 8 independent f32x2 FMA chains. Per-candidate numerics are
// identical to the previous version; candidates inserted in index order so
// top-k tie semantics (sortable u64 key, evict max) are unchanged.
// ---------------------------------------------------------------------------
__global__ __launch_bounds__(128) void k_knn(int src)
{
    const float* h = src ? g_hB : g_hA;
    __shared__ __align__(16) float tile[64*64];   // 16 KB candidate tile
    __shared__ ull kept[KK][128];                 // 16 KB
    __shared__ float sqt[64];

    int tid = threadIdx.x;
    int b   = blockIdx.y;
    int n   = blockIdx.x*128 + tid;
    int row = b*NN + n;

    ull hq[32];
    {
        const longlong2* hp = reinterpret_cast<const longlong2*>(h + row*HH);
        #pragma unroll
        for (int q = 0; q < 16; q++){
            longlong2 v = hp[q];
            hq[2*q]   = (ull)v.x;
            hq[2*q+1] = (ull)v.y;
        }
    }
    float sqn = g_sq[row];

    #pragma unroll
    for (int j = 0; j < KK; j++) kept[j][tid] = ~0ull;
    ull wkey = ~0ull;
    int ws = 0;

    for (int t = 0; t < 8; t++){
        __syncthreads();
        const float4* s4 = reinterpret_cast<const float4*>(h + (b*NN + t*64)*HH);
        float4* t4 = reinterpret_cast<float4*>(tile);
        #pragma unroll
        for (int i = 0; i < 8; i++) t4[tid + i*128] = s4[tid + i*128];
        if (tid < 64) sqt[tid] = g_sq[b*NN + t*64 + tid];
        __syncthreads();

        #pragma unroll 1
        for (int mm = 0; mm < 64; mm += 2){
            const longlong2* tp0 = reinterpret_cast<const longlong2*>(tile + mm*64);
            const longlong2* tp1 = reinterpret_cast<const longlong2*>(tile + (mm+1)*64);
            ull a0=0, a1=0, a2=0, a3=0;
            ull c0=0, c1=0, c2=0, c3=0;
            #pragma unroll
            for (int q = 0; q < 8; q++){
                longlong2 v = tp0[q], w = tp1[q];
                a0 = fma2(hq[2*q],   (ull)v.x, a0);
                a1 = fma2(hq[2*q+1], (ull)v.y, a1);
                c0 = fma2(hq[2*q],   (ull)w.x, c0);
                c1 = fma2(hq[2*q+1], (ull)w.y, c1);
            }
            #pragma unroll
            for (int q = 8; q < 16; q++){
                longlong2 v = tp0[q], w = tp1[q];
                a2 = fma2(hq[2*q],   (ull)v.x, a2);
                a3 = fma2(hq[2*q+1], (ull)v.y, a3);
                c2 = fma2(hq[2*q],   (ull)w.x, c2);
                c3 = fma2(hq[2*q+1], (ull)w.y, c3);
            }
            ull sa = add2(add2(a0,a2), add2(a1,a3));
            ull sc = add2(add2(c0,c2), add2(c1,c3));
            float dot0 = lo2(sa) + hi2(sa);
            float dot1 = lo2(sc) + hi2(sc);
            float d0 = sqn + sqt[mm]   - 2.0f*dot0;
            float d1 = sqn + sqt[mm+1] - 2.0f*dot1;
            unsigned u0 = __float_as_uint(d0);
            u0 ^= (unsigned)((int)u0 >> 31) | 0x80000000u;
            unsigned u1 = __float_as_uint(d1);
            u1 ^= (unsigned)((int)u1 >> 31) | 0x80000000u;
            ull k0 = ((ull)u0 << 32) | (unsigned)(t*64 + mm);
            ull k1 = ((ull)u1 << 32) | (unsigned)(t*64 + mm + 1);

            if (k0 < wkey){
                kept[ws][tid] = k0;
                ull mx = kept[0][tid]; int ms = 0;
                #pragma unroll
                for (int j = 1; j < KK; j++){
                    ull kj = kept[j][tid];
                    if (kj > mx){ mx = kj; ms = j; }
                }
                wkey = mx; ws = ms;
            }
            if (k1 < wkey){
                kept[ws][tid] = k1;
                ull mx = kept[0][tid]; int ms = 0;
                #pragma unroll
                for (int j = 1; j < KK; j++){
                    ull kj = kept[j][tid];
                    if (kj > mx){ mx = kj; ms = j; }
                }
                wkey = mx; ws = ms;
            }
        }
    }
    #pragma unroll
    for (int j = 0; j < KK; j++)
        g_idx[row*KK + j] = b*NN + (int)(unsigned)(kept[j][tid] & 0xffffffffull);
}

// ---------------------------------------------------------------------------
// a/c GEMM: ac[p][0:64] = A_w h_p + b ; ac[p][64:128] = C_w h_p
// ---------------------------------------------------------------------------
__global__ __launch_bounds__(128) void k_ac(int r, int src)
{
    const float* h = src ? g_hB : g_hA;
    __shared__ __align__(16) float hs[64*HH];   // 16 KB
    int t  = threadIdx.x;
    int p0 = blockIdx.x*64;

    ull wq[32];
    const float* wbase = g_wfT + r*8192;
    #pragma unroll
    for (int j = 0; j < 32; j++){
        float wa = wbase[(2*j  )*128 + t];
        float wb = wbase[(2*j+1)*128 + t];
        wq[j] = pk2(wa, wb);
    }
    float bias = (t < HH) ? g_wb[r*HH + t] : 0.f;

    const float4* src4 = reinterpret_cast<const float4*>(h + p0*HH);
    float4* hs4 = reinterpret_cast<float4*>(hs);
    for (int i = t; i < 1024; i += 128) hs4[i] = src4[i];
    __syncthreads();

    #pragma unroll 2
    for (int p = 0; p < 64; p++){
        const longlong2* hp = reinterpret_cast<const longlong2*>(hs + p*HH);
        ull a0=0, a1=0, a2=0, a3=0;
        #pragma unroll
        for (int q = 0; q < 8; q++){
            longlong2 v = hp[q];
            a0 = fma2(wq[2*q],   (ull)v.x, a0);
            a1 = fma2(wq[2*q+1], (ull)v.y, a1);
        }
        #pragma unroll
        for (int q = 8; q < 16; q++){
            longlong2 v = hp[q];
            a2 = fma2(wq[2*q],   (ull)v.x, a2);
            a3 = fma2(wq[2*q+1], (ull)v.y, a3);
        }
        ull sv = add2(add2(a0,a2), add2(a1,a3));
        g_ac[(p0+p)*128 + t] = bias + lo2(sv) + hi2(sv);
    }
}

// ---------------------------------------------------------------------------
// gather-max + fused row-norm of the output (feeds next round's kNN).
// ---------------------------------------------------------------------------
__global__ void k_gmax(int src)
{
    float* out = src ? g_hA : g_hB;
    __shared__ int idxs[8*KK];
    __shared__ float part[16];
    int tx = threadIdx.x, ty = threadIdx.y;
    int tid = ty*64 + tx;
    int p0 = blockIdx.x*8;
    if (tid < 8*KK) idxs[tid] = g_idx[p0*KK + tid];
    __syncthreads();
    int p = p0 + ty;
    float a = g_ac[p*128 + tx];
    float m = 0.f;                        // relu => candidates clamped at 0
    #pragma unroll
    for (int k = 0; k < KK; k++){
        int nb = idxs[ty*KK + k];
        m = fmaxf(m, a + g_ac[nb*128 + 64 + tx]);
    }
    out[p*HH + tx] = m;

    float ss = m*m;
    #pragma unroll
    for (int off = 16; off; off >>= 1) ss += __shfl_down_sync(0xffffffffu, ss, off);
    if ((tx & 31) == 0) part[tid >> 5] = ss;
    __syncthreads();
    if (tx == 0) g_sq[p] = part[2*ty] + part[2*ty + 1];
}

// ---------------------------------------------------------------------------
// head: u = relu(bn(W_s1 h)); logit = w_s2 . u + b_s2
// ---------------------------------------------------------------------------
__global__ void k_head(int src,
    const float* __restrict__ w1, const float* __restrict__ g1,
    const float* __restrict__ b1,
    const float* __restrict__ w2, const float* __restrict__ b2,
    float* __restrict__ out)
{
    const float* h = src ? g_hB : g_hA;
    __shared__ float w1sT[HH][HH];
    __shared__ __align__(16) float hs[16][HH];
    __shared__ float parts[16][2];
    int tx = threadIdx.x, ty = threadIdx.y;
    int tid = ty*64 + tx;
    int p0 = blockIdx.x*16;

    for (int i = tid; i < HH*HH; i += 1024){ int o = i>>6, hh = i&63; w1sT[hh][o] = w1[i]; }
    hs[ty][tx] = h[(p0+ty)*HH + tx];
    __syncthreads();

    float inv = rsqrtf(1.0f + EPSF);
    float s = g1[tx]*inv, bb = b1[tx];
    float a0=0,a1=0,a2=0,a3=0;
    const float4* hp = reinterpret_cast<const float4*>(hs[ty]);
    #pragma unroll
    for (int q = 0; q < 16; q++){
        float4 v = hp[q];
        int hh = q*4;
        a0 = fmaf(w1sT[hh+0][tx], v.x, a0);
        a1 = fmaf(w1sT[hh+1][tx], v.y, a1);
        a2 = fmaf(w1sT[hh+2][tx], v.z, a2);
        a3 = fmaf(w1sT[hh+3][tx], v.w, a3);
    }
    float u = fmaxf(((a0+a1)+(a2+a3))*s + bb, 0.f);
    float v = u * w2[tx];
    #pragma unroll
    for (int off = 16; off; off >>= 1) v += __shfl_down_sync(0xffffffffu, v, off);
    if ((tx & 31) == 0) parts[ty][tx >> 5] = v;
    __syncthreads();
    if (tx == 0) out[p0 + ty] = parts[ty][0] + parts[ty][1] + b2[0];
}

// ---------------------------------------------------------------------------
extern "C" void kernel_launch(void* const* d_in, const int* in_sizes, int n_in,
                              void* d_out, int out_size)
{
    (void)in_sizes; (void)n_in; (void)out_size;
    const float* x    = (const float*)d_in[0];
    const float* w_t1 = (const float*)d_in[1];
    const float* g_t1 = (const float*)d_in[2];
    const float* b_t1 = (const float*)d_in[3];
    const float* w_t2 = (const float*)d_in[4];
    const float* g_t2 = (const float*)d_in[5];
    const float* b_t2 = (const float*)d_in[6];
    const float* w_nb = (const float*)d_in[7];
    const float* g_nb = (const float*)d_in[8];
    const float* b_nb = (const float*)d_in[9];
    const float* w_s1 = (const float*)d_in[10];
    const float* g_s1 = (const float*)d_in[11];
    const float* b_s1 = (const float*)d_in[12];
    const float* w_s2 = (const float*)d_in[13];
    const float* b_s2 = (const float*)d_in[14];
    float* out = (float*)d_out;

    k_prep<<<64, 256>>>(w_nb, g_nb, b_nb);
    k_input<<<BB*NN/16, dim3(64,16)>>>(x, w_t1, g_t1, b_t1, w_t2, g_t2, b_t2);

    for (int r = 0; r < 2; r++){
        // r==0: read g_hA, write g_hB ; r==1: read g_hB, write g_hA
        k_knn <<<dim3(4,128), 128>>>(r);
        k_ac  <<<BB*NN/64, 128>>>(r, r);
        k_gmax<<<BB*NN/8, dim3(64,8)>>>(r);
    }

    k_head<<<BB*NN/16, dim3(64,16)>>>(0, w_s1, g_s1, b_s1, w_s2, b_s2, out);
}

// round 7
// speedup vs baseline: 1.2226x; 1.2226x over previous
#include <cuda_runtime.h>

#define BB 128
#define NN 512
#define CC 7
#define HH 64
#define KK 16
#define EPSF 1e-5f

typedef unsigned long long ull;

// ---------------- scratch (device globals: allocation-free) ----------------
__device__ __align__(16) float g_hA[BB*NN*HH];      // 16.8 MB
__device__ __align__(16) float g_hB[BB*NN*HH];      // 16.8 MB
__device__ __align__(16) float g_ac[BB*NN*2*HH];    // 33.5 MB  [point][0:64]=a, [64:128]=c
__device__ float g_sq[BB*NN];
__device__ int   g_idx[BB*NN*KK];
__device__ float g_wfT[2*HH*128];                   // folded weights, [r][hh][o] (transposed)
__device__ float g_wb[2*HH];                        // folded bias

// ---------------- packed fp32x2 helpers (Blackwell f32x2 pipe) -------------
__device__ __forceinline__ ull fma2(ull a, ull b, ull c){
    ull d; asm("fma.rn.f32x2 %0, %1, %2, %3;" : "=l"(d) : "l"(a), "l"(b), "l"(c)); return d;
}
__device__ __forceinline__ ull add2(ull a, ull b){
    ull d; asm("add.rn.f32x2 %0, %1, %2;" : "=l"(d) : "l"(a), "l"(b)); return d;
}
__device__ __forceinline__ float lo2(ull a){ return __uint_as_float((unsigned)a); }
__device__ __forceinline__ float hi2(ull a){ return __uint_as_float((unsigned)(a >> 32)); }
__device__ __forceinline__ ull pk2(float lo, float hi){
    ull d; asm("mov.b64 %0, {%1,%2};" : "=l"(d) : "f"(lo), "f"(hi)); return d;
}

// ---------------------------------------------------------------------------
// k_prep: fold BN scale into edgeconv weights, TRANSPOSED layout [r][hh][o]
// ---------------------------------------------------------------------------
__global__ void k_prep(const float* __restrict__ wnb,
                       const float* __restrict__ gnb,
                       const float* __restrict__ bnb)
{
    int i = blockIdx.x*256 + threadIdx.x;
    if (i < 2*HH) g_wb[i] = bnb[i];
    if (i >= 2*HH*128) return;
    int r   = i >> 13;
    int rem = i & 8191;
    int hh  = rem >> 7;
    int o   = rem & 127;
    float inv = rsqrtf(1.0f + EPSF);
    float v;
    if (o < HH){
        float s = gnb[r*HH + o] * inv;
        v = (wnb[(r*HH + o)*128 + hh] - wnb[(r*HH + o)*128 + 64 + hh]) * s;
    } else {
        int oo = o - HH;
        float s = gnb[r*HH + oo] * inv;
        v = wnb[(r*HH + oo)*128 + 64 + hh] * s;
    }
    g_wfT[i] = v;
}

// ---------------------------------------------------------------------------
// k_input: h = relu(bn2(W2 relu(bn1(W1 x)))), fused row-norm (g_sq).
// ---------------------------------------------------------------------------
__global__ void k_input(const float* __restrict__ x,
                        const float* __restrict__ w1, const float* __restrict__ g1,
                        const float* __restrict__ b1,
                        const float* __restrict__ w2, const float* __restrict__ g2,
                        const float* __restrict__ b2)
{
    __shared__ float w1s[HH*CC];
    __shared__ float w2sT[HH][HH];
    __shared__ float xs[16][CC];
    __shared__ __align__(16) float h1s[16][HH];
    __shared__ float part[32];
    int tx = threadIdx.x, ty = threadIdx.y;
    int tid = ty*64 + tx;
    int p0 = blockIdx.x*16;
    int b  = p0 / NN;
    int n0 = p0 % NN;

    for (int i = tid; i < HH*CC; i += 1024) w1s[i] = w1[i];
    for (int i = tid; i < HH*HH; i += 1024) { int o = i>>6, hh = i&63; w2sT[hh][o] = w2[i]; }
    if (tid < 16*CC) { int c = tid/16, i = tid%16; xs[i][c] = x[b*CC*NN + c*NN + n0 + i]; }
    __syncthreads();

    float inv = rsqrtf(1.0f + EPSF);
    float s1 = g1[tx]*inv, bb1 = b1[tx];
    float s2 = g2[tx]*inv, bb2 = b2[tx];

    {
        float acc = 0.f;
        #pragma unroll
        for (int c = 0; c < CC; c++) acc = fmaf(w1s[tx*CC + c], xs[ty][c], acc);
        h1s[ty][tx] = fmaxf(acc*s1 + bb1, 0.f);
    }
    __syncthreads();
    float val;
    {
        float a0=0,a1=0,a2=0,a3=0;
        const float4* hp = reinterpret_cast<const float4*>(h1s[ty]);
        #pragma unroll
        for (int q = 0; q < 16; q++){
            float4 v = hp[q];
            int hh = q*4;
            a0 = fmaf(w2sT[hh+0][tx], v.x, a0);
            a1 = fmaf(w2sT[hh+1][tx], v.y, a1);
            a2 = fmaf(w2sT[hh+2][tx], v.z, a2);
            a3 = fmaf(w2sT[hh+3][tx], v.w, a3);
        }
        val = fmaxf(((a0+a1)+(a2+a3))*s2 + bb2, 0.f);
        g_hA[(p0+ty)*HH + tx] = val;
    }
    float ss = val*val;
    #pragma unroll
    for (int off = 16; off; off >>= 1) ss += __shfl_down_sync(0xffffffffu, ss, off);
    if ((tx & 31) == 0) part[tid >> 5] = ss;
    __syncthreads();
    if (tx == 0) g_sq[p0 + ty] = part[2*ty] + part[2*ty + 1];
}

// ---------------------------------------------------------------------------
// kNN v3: 64 queries/block, software-pipelined distance-vs-insert, split-scan
// top-16 (per-half max in registers, 8-entry smem rescan). Keys are unique
// (index in low bits) so evict-max-with-strict-less reproduces jax.lax.top_k
// tie semantics exactly. d clamped at 0 (math guarantees d>=0; clamp only
// affects self/duplicate rounding, resolved by index as before).
// ---------------------------------------------------------------------------
__global__ __launch_bounds__(64) void k_knn(int src)
{
    const float* h = src ? g_hB : g_hA;
    __shared__ __align__(16) float tile[64*64];   // 16 KB candidate tile
    __shared__ ull kept[KK][64];                  // 8 KB
    __shared__ float sqt[64];

    int tid = threadIdx.x;
    int b   = blockIdx.y;
    int n   = blockIdx.x*64 + tid;
    int row = b*NN + n;

    ull hq[32];
    {
        const longlong2* hp = reinterpret_cast<const longlong2*>(h + row*HH);
        #pragma unroll
        for (int q = 0; q < 16; q++){
            longlong2 v = hp[q];
            hq[2*q]   = (ull)v.x;
            hq[2*q+1] = (ull)v.y;
        }
    }
    float sqn = g_sq[row];

    ull* keptc = &kept[0][tid];                   // column base, stride 64
    #pragma unroll
    for (int j = 0; j < KK; j++) keptc[j*64] = ~0ull;
    ull maxA = ~0ull, maxB = ~0ull;               // per-half running max (regs)
    int wsA = 0, wsB = 0;

    // distance -> sortable key for candidate index mc within this tile-loop
    #define DIST_KEY(mc, keyout) {                                            \
        const longlong2* tp = reinterpret_cast<const longlong2*>(tile + (mc)*64); \
        ull a0=0, a1=0, a2=0, a3=0;                                           \
        _Pragma("unroll")                                                     \
        for (int q = 0; q < 8; q++){                                          \
            longlong2 v = tp[q];                                              \
            a0 = fma2(hq[2*q],   (ull)v.x, a0);                               \
            a1 = fma2(hq[2*q+1], (ull)v.y, a1);                               \
        }                                                                     \
        _Pragma("unroll")                                                     \
        for (int q = 8; q < 16; q++){                                         \
            longlong2 v = tp[q];                                              \
            a2 = fma2(hq[2*q],   (ull)v.x, a2);                               \
            a3 = fma2(hq[2*q+1], (ull)v.y, a3);                               \
        }                                                                     \
        ull sv = add2(add2(a0,a2), add2(a1,a3));                              \
        float dot = lo2(sv) + hi2(sv);                                        \
        float d = fmaxf(sqn + sqt[mc] - 2.0f*dot, 0.f);                       \
        keyout = ((ull)__float_as_uint(d) << 32) | (unsigned)(t*64 + (mc));   \
    }

    #define INSERT(key) {                                                     \
        ull wk = (maxA > maxB) ? maxA : maxB;                                 \
        if ((key) < wk){                                                      \
            bool ina = (maxA > maxB);                                         \
            int base = ina ? 0 : 8;                                           \
            int ws   = ina ? wsA : wsB;                                       \
            keptc[(base + ws)*64] = (key);                                    \
            ull mx = keptc[base*64]; int ms = 0;                              \
            _Pragma("unroll")                                                 \
            for (int j = 1; j < 8; j++){                                      \
                ull kj = keptc[(base + j)*64];                                \
                if (kj > mx){ mx = kj; ms = j; }                              \
            }                                                                 \
            if (ina){ maxA = mx; wsA = ms; } else { maxB = mx; wsB = ms; }    \
        }                                                                     \
    }

    for (int t = 0; t < 8; t++){
        __syncthreads();
        const float4* s4 = reinterpret_cast<const float4*>(h + (b*NN + t*64)*HH);
        float4* t4 = reinterpret_cast<float4*>(tile);
        #pragma unroll
        for (int i = 0; i < 16; i++) t4[tid + i*64] = s4[tid + i*64];
        sqt[tid] = g_sq[b*NN + t*64 + tid];
        __syncthreads();

        // software pipeline: distance of mm+1 overlaps insert of mm
        ull kcur;
        DIST_KEY(0, kcur);
        #pragma unroll 1
        for (int mm = 0; mm < 63; mm++){
            ull knext;
            DIST_KEY(mm+1, knext);
            INSERT(kcur);
            kcur = knext;
        }
        INSERT(kcur);
    }
    #undef DIST_KEY
    #undef INSERT

    #pragma unroll
    for (int j = 0; j < KK; j++)
        g_idx[row*KK + j] = b*NN + (int)(unsigned)(keptc[j*64] & 0xffffffffull);
}

// ---------------------------------------------------------------------------
// a/c GEMM: ac[p][0:64] = A_w h_p + b ; ac[p][64:128] = C_w h_p
// ---------------------------------------------------------------------------
__global__ __launch_bounds__(128) void k_ac(int r, int src)
{
    const float* h = src ? g_hB : g_hA;
    __shared__ __align__(16) float hs[64*HH];   // 16 KB
    int t  = threadIdx.x;
    int p0 = blockIdx.x*64;

    ull wq[32];
    const float* wbase = g_wfT + r*8192;
    #pragma unroll
    for (int j = 0; j < 32; j++){
        float wa = wbase[(2*j  )*128 + t];
        float wb = wbase[(2*j+1)*128 + t];
        wq[j] = pk2(wa, wb);
    }
    float bias = (t < HH) ? g_wb[r*HH + t] : 0.f;

    const float4* src4 = reinterpret_cast<const float4*>(h + p0*HH);
    float4* hs4 = reinterpret_cast<float4*>(hs);
    for (int i = t; i < 1024; i += 128) hs4[i] = src4[i];
    __syncthreads();

    #pragma unroll 2
    for (int p = 0; p < 64; p++){
        const longlong2* hp = reinterpret_cast<const longlong2*>(hs + p*HH);
        ull a0=0, a1=0, a2=0, a3=0;
        #pragma unroll
        for (int q = 0; q < 8; q++){
            longlong2 v = hp[q];
            a0 = fma2(wq[2*q],   (ull)v.x, a0);
            a1 = fma2(wq[2*q+1], (ull)v.y, a1);
        }
        #pragma unroll
        for (int q = 8; q < 16; q++){
            longlong2 v = hp[q];
            a2 = fma2(wq[2*q],   (ull)v.x, a2);
            a3 = fma2(wq[2*q+1], (ull)v.y, a3);
        }
        ull sv = add2(add2(a0,a2), add2(a1,a3));
        g_ac[(p0+p)*128 + t] = bias + lo2(sv) + hi2(sv);
    }
}

// ---------------------------------------------------------------------------
// gather-max + fused row-norm of the output (feeds next round's kNN).
// ---------------------------------------------------------------------------
__global__ void k_gmax(int src)
{
    float* out = src ? g_hA : g_hB;
    __shared__ int idxs[8*KK];
    __shared__ float part[16];
    int tx = threadIdx.x, ty = threadIdx.y;
    int tid = ty*64 + tx;
    int p0 = blockIdx.x*8;
    if (tid < 8*KK) idxs[tid] = g_idx[p0*KK + tid];
    __syncthreads();
    int p = p0 + ty;
    float a = g_ac[p*128 + tx];
    float m = 0.f;                        // relu => candidates clamped at 0
    #pragma unroll
    for (int k = 0; k < KK; k++){
        int nb = idxs[ty*KK + k];
        m = fmaxf(m, a + g_ac[nb*128 + 64 + tx]);
    }
    out[p*HH + tx] = m;

    float ss = m*m;
    #pragma unroll
    for (int off = 16; off; off >>= 1) ss += __shfl_down_sync(0xffffffffu, ss, off);
    if ((tx & 31) == 0) part[tid >> 5] = ss;
    __syncthreads();
    if (tx == 0) g_sq[p] = part[2*ty] + part[2*ty + 1];
}

// ---------------------------------------------------------------------------
// head: u = relu(bn(W_s1 h)); logit = w_s2 . u + b_s2
// ---------------------------------------------------------------------------
__global__ void k_head(int src,
    const float* __restrict__ w1, const float* __restrict__ g1,
    const float* __restrict__ b1,
    const float* __restrict__ w2, const float* __restrict__ b2,
    float* __restrict__ out)
{
    const float* h = src ? g_hB : g_hA;
    __shared__ float w1sT[HH][HH];
    __shared__ __align__(16) float hs[16][HH];
    __shared__ float parts[16][2];
    int tx = threadIdx.x, ty = threadIdx.y;
    int tid = ty*64 + tx;
    int p0 = blockIdx.x*16;

    for (int i = tid; i < HH*HH; i += 1024){ int o = i>>6, hh = i&63; w1sT[hh][o] = w1[i]; }
    hs[ty][tx] = h[(p0+ty)*HH + tx];
    __syncthreads();

    float inv = rsqrtf(1.0f + EPSF);
    float s = g1[tx]*inv, bb = b1[tx];
    float a0=0,a1=0,a2=0,a3=0;
    const float4* hp = reinterpret_cast<const float4*>(hs[ty]);
    #pragma unroll
    for (int q = 0; q < 16; q++){
        float4 v = hp[q];
        int hh = q*4;
        a0 = fmaf(w1sT[hh+0][tx], v.x, a0);
        a1 = fmaf(w1sT[hh+1][tx], v.y, a1);
        a2 = fmaf(w1sT[hh+2][tx], v.z, a2);
        a3 = fmaf(w1sT[hh+3][tx], v.w, a3);
    }
    float u = fmaxf(((a0+a1)+(a2+a3))*s + bb, 0.f);
    float v = u * w2[tx];
    #pragma unroll
    for (int off = 16; off; off >>= 1) v += __shfl_down_sync(0xffffffffu, v, off);
    if ((tx & 31) == 0) parts[ty][tx >> 5] = v;
    __syncthreads();
    if (tx == 0) out[p0 + ty] = parts[ty][0] + parts[ty][1] + b2[0];
}

// ---------------------------------------------------------------------------
extern "C" void kernel_launch(void* const* d_in, const int* in_sizes, int n_in,
                              void* d_out, int out_size)
{
    (void)in_sizes; (void)n_in; (void)out_size;
    const float* x    = (const float*)d_in[0];
    const float* w_t1 = (const float*)d_in[1];
    const float* g_t1 = (const float*)d_in[2];
    const float* b_t1 = (const float*)d_in[3];
    const float* w_t2 = (const float*)d_in[4];
    const float* g_t2 = (const float*)d_in[5];
    const float* b_t2 = (const float*)d_in[6];
    const float* w_nb = (const float*)d_in[7];
    const float* g_nb = (const float*)d_in[8];
    const float* b_nb = (const float*)d_in[9];
    const float* w_s1 = (const float*)d_in[10];
    const float* g_s1 = (const float*)d_in[11];
    const float* b_s1 = (const float*)d_in[12];
    const float* w_s2 = (const float*)d_in[13];
    const float* b_s2 = (const float*)d_in[14];
    float* out = (float*)d_out;

    k_prep<<<64, 256>>>(w_nb, g_nb, b_nb);
    k_input<<<BB*NN/16, dim3(64,16)>>>(x, w_t1, g_t1, b_t1, w_t2, g_t2, b_t2);

    for (int r = 0; r < 2; r++){
        // r==0: read g_hA, write g_hB ; r==1: read g_hB, write g_hA
        k_knn <<<dim3(8,128), 64>>>(r);
        k_ac  <<<BB*NN/64, 128>>>(r, r);
        k_gmax<<<BB*NN/8, dim3(64,8)>>>(r);
    }

    k_head<<<BB*NN/16, dim3(64,16)>>>(0, w_s1, g_s1, b_s1, w_s2, b_s2, out);
}

// round 10
// speedup vs baseline: 1.2861x; 1.0519x over previous
#include <cuda_runtime.h>

#define BB 128
#define NN 512
#define CC 7
#define HH 64
#define KK 16
#define EPSF 1e-5f

typedef unsigned long long ull;

// ---------------- scratch (device globals: allocation-free) ----------------
__device__ __align__(16) float g_hA[BB*NN*HH];      // 16.8 MB
__device__ __align__(16) float g_hB[BB*NN*HH];      // 16.8 MB
__device__ __align__(16) float g_ac[BB*NN*2*HH];    // 33.5 MB  [point][0:64]=a, [64:128]=c
__device__ float g_sq[BB*NN];
__device__ int   g_idx[BB*NN*KK];
__device__ float g_wfT[2*HH*128];                   // folded weights, [r][hh][o] (transposed)
__device__ float g_wb[2*HH];                        // folded bias

// ---------------- packed fp32x2 helpers (Blackwell f32x2 pipe) -------------
__device__ __forceinline__ ull fma2(ull a, ull b, ull c){
    ull d; asm("fma.rn.f32x2 %0, %1, %2, %3;" : "=l"(d) : "l"(a), "l"(b), "l"(c)); return d;
}
__device__ __forceinline__ ull add2(ull a, ull b){
    ull d; asm("add.rn.f32x2 %0, %1, %2;" : "=l"(d) : "l"(a), "l"(b)); return d;
}
__device__ __forceinline__ float lo2(ull a){ return __uint_as_float((unsigned)a); }
__device__ __forceinline__ float hi2(ull a){ return __uint_as_float((unsigned)(a >> 32)); }
__device__ __forceinline__ ull pk2(float lo, float hi){
    ull d; asm("mov.b64 %0, {%1,%2};" : "=l"(d) : "f"(lo), "f"(hi)); return d;
}

// ---------------------------------------------------------------------------
// k_prep: fold BN scale into edgeconv weights, TRANSPOSED layout [r][hh][o]
// ---------------------------------------------------------------------------
__global__ void k_prep(const float* __restrict__ wnb,
                       const float* __restrict__ gnb,
                       const float* __restrict__ bnb)
{
    int i = blockIdx.x*256 + threadIdx.x;
    if (i < 2*HH) g_wb[i] = bnb[i];
    if (i >= 2*HH*128) return;
    int r   = i >> 13;
    int rem = i & 8191;
    int hh  = rem >> 7;
    int o   = rem & 127;
    float inv = rsqrtf(1.0f + EPSF);
    float v;
    if (o < HH){
        float s = gnb[r*HH + o] * inv;
        v = (wnb[(r*HH + o)*128 + hh] - wnb[(r*HH + o)*128 + 64 + hh]) * s;
    } else {
        int oo = o - HH;
        float s = gnb[r*HH + oo] * inv;
        v = wnb[(r*HH + oo)*128 + 64 + hh] * s;
    }
    g_wfT[i] = v;
}

// ---------------------------------------------------------------------------
// k_input: h = relu(bn2(W2 relu(bn1(W1 x)))), fused row-norm (g_sq).
// ---------------------------------------------------------------------------
__global__ void k_input(const float* __restrict__ x,
                        const float* __restrict__ w1, const float* __restrict__ g1,
                        const float* __restrict__ b1,
                        const float* __restrict__ w2, const float* __restrict__ g2,
                        const float* __restrict__ b2)
{
    __shared__ float w1s[HH*CC];
    __shared__ float w2sT[HH][HH];
    __shared__ float xs[16][CC];
    __shared__ __align__(16) float h1s[16][HH];
    __shared__ float part[32];
    int tx = threadIdx.x, ty = threadIdx.y;
    int tid = ty*64 + tx;
    int p0 = blockIdx.x*16;
    int b  = p0 / NN;
    int n0 = p0 % NN;

    for (int i = tid; i < HH*CC; i += 1024) w1s[i] = w1[i];
    for (int i = tid; i < HH*HH; i += 1024) { int o = i>>6, hh = i&63; w2sT[hh][o] = w2[i]; }
    if (tid < 16*CC) { int c = tid/16, i = tid%16; xs[i][c] = x[b*CC*NN + c*NN + n0 + i]; }
    __syncthreads();

    float inv = rsqrtf(1.0f + EPSF);
    float s1 = g1[tx]*inv, bb1 = b1[tx];
    float s2 = g2[tx]*inv, bb2 = b2[tx];

    {
        float acc = 0.f;
        #pragma unroll
        for (int c = 0; c < CC; c++) acc = fmaf(w1s[tx*CC + c], xs[ty][c], acc);
        h1s[ty][tx] = fmaxf(acc*s1 + bb1, 0.f);
    }
    __syncthreads();
    float val;
    {
        float a0=0,a1=0,a2=0,a3=0;
        const float4* hp = reinterpret_cast<const float4*>(h1s[ty]);
        #pragma unroll
        for (int q = 0; q < 16; q++){
            float4 v = hp[q];
            int hh = q*4;
            a0 = fmaf(w2sT[hh+0][tx], v.x, a0);
            a1 = fmaf(w2sT[hh+1][tx], v.y, a1);
            a2 = fmaf(w2sT[hh+2][tx], v.z, a2);
            a3 = fmaf(w2sT[hh+3][tx], v.w, a3);
        }
        val = fmaxf(((a0+a1)+(a2+a3))*s2 + bb2, 0.f);
        g_hA[(p0+ty)*HH + tx] = val;
    }
    float ss = val*val;
    #pragma unroll
    for (int off = 16; off; off >>= 1) ss += __shfl_down_sync(0xffffffffu, ss, off);
    if ((tx & 31) == 0) part[tid >> 5] = ss;
    __syncthreads();
    if (tx == 0) g_sq[p0 + ty] = part[2*ty] + part[2*ty + 1];
}

// ---------------------------------------------------------------------------
// kNN v4: filter + batch-rebuild selection.
// Per candidate: distance (f32x2, identical numerics to v3) + BRANCHLESS
// predicated append to a smem buffer when key < running threshold. The
// threshold only tightens at rare, warp-uniform rebuilds (evict-max over the
// buffered keys, same structure as v3). Exact: keys unique (index in low
// bits), appended in index order, strict '<' => identical top-16 set and
// jax.lax.top_k tie semantics. Output order irrelevant (feeds a max).
// ---------------------------------------------------------------------------
#define CAP 24            // buffer slots per thread (slot CAP-1 = dummy sink)
__global__ __launch_bounds__(64) void k_knn(int src)
{
    const float* h = src ? g_hB : g_hA;
    __shared__ __align__(16) float tile[64*64];   // 16 KB candidate tile
    __shared__ ull keep[KK][64];                  // 8 KB  top-16 structure
    __shared__ ull buf[CAP][64];                  // 12 KB append buffer
    __shared__ float sqt[64];

    int tid = threadIdx.x;
    int b   = blockIdx.y;
    int n   = blockIdx.x*64 + tid;
    int row = b*NN + n;

    ull hq[32];
    {
        const longlong2* hp = reinterpret_cast<const longlong2*>(h + row*HH);
        #pragma unroll
        for (int q = 0; q < 16; q++){
            longlong2 v = hp[q];
            hq[2*q]   = (ull)v.x;
            hq[2*q+1] = (ull)v.y;
        }
    }
    float sqn = g_sq[row];

    ull* keepc = &keep[0][tid];                   // column base, stride 64
    ull* bufc  = &buf[0][tid];
    #pragma unroll
    for (int j = 0; j < KK; j++) keepc[j*64] = ~0ull;
    ull maxA = ~0ull, maxB = ~0ull;               // per-half running max (regs)
    int wsA = 0, wsB = 0;
    ull wkey = ~0ull;                             // stale-but-safe threshold
    int cnt = 0;

    #define DIST_KEY(mc, keyout) {                                            \
        const longlong2* tp = reinterpret_cast<const longlong2*>(tile + (mc)*64); \
        ull a0=0, a1=0, a2=0, a3=0;                                           \
        _Pragma("unroll")                                                     \
        for (int q = 0; q < 8; q++){                                          \
            longlong2 v = tp[q];                                              \
            a0 = fma2(hq[2*q],   (ull)v.x, a0);                               \
            a1 = fma2(hq[2*q+1], (ull)v.y, a1);                               \
        }                                                                     \
        _Pragma("unroll")                                                     \
        for (int q = 8; q < 16; q++){                                         \
            longlong2 v = tp[q];                                              \
            a2 = fma2(hq[2*q],   (ull)v.x, a2);                               \
            a3 = fma2(hq[2*q+1], (ull)v.y, a3);                               \
        }                                                                     \
        ull sv = add2(add2(a0,a2), add2(a1,a3));                              \
        float dot = lo2(sv) + hi2(sv);                                        \
        float d = fmaxf(sqn + sqt[mc] - 2.0f*dot, 0.f);                       \
        keyout = ((ull)__float_as_uint(d) << 32) | (unsigned)(t*64 + (mc));   \
    }

    // branchless append: always store (dummy slot when rejected)
    #define APPEND(key) {                                                     \
        int pass = ((key) < wkey);                                            \
        int slot = pass ? cnt : (CAP-1);                                      \
        bufc[slot*64] = (key);                                                \
        cnt += pass;                                                          \
    }

    // evict-max insert into the 16-slot keep structure (split-scan, as v3)
    #define INSERT(key) {                                                     \
        ull wk = (maxA > maxB) ? maxA : maxB;                                 \
        if ((key) < wk){                                                      \
            bool ina = (maxA > maxB);                                         \
            int base = ina ? 0 : 8;                                           \
            int ws   = ina ? wsA : wsB;                                       \
            keepc[(base + ws)*64] = (key);                                    \
            ull mx = keepc[base*64]; int ms = 0;                              \
            _Pragma("unroll")                                                 \
            for (int j = 1; j < 8; j++){                                      \
                ull kj = keepc[(base + j)*64];                                \
                if (kj > mx){ mx = kj; ms = j; }                              \
            }                                                                 \
            if (ina){ maxA = mx; wsA = ms; } else { maxB = mx; wsB = ms; }    \
        }                                                                     \
    }

    // warp-uniform rebuild: fold buffered keys into keep, tighten threshold
    #define REBUILD() {                                                       \
        int vm = (int)__reduce_max_sync(0xffffffffu, (unsigned)cnt);          \
        for (int j = 0; j < vm; j++){                                         \
            ull kk = (j < cnt) ? bufc[j*64] : ~0ull;                          \
            INSERT(kk);                                                       \
        }                                                                     \
        wkey = (maxA > maxB) ? maxA : maxB;                                   \
        cnt = 0;                                                              \
    }

    for (int t = 0; t < 8; t++){
        __syncthreads();
        const float4* s4 = reinterpret_cast<const float4*>(h + (b*NN + t*64)*HH);
        float4* t4 = reinterpret_cast<float4*>(tile);
        #pragma unroll
        for (int i = 0; i < 16; i++) t4[tid + i*64] = s4[tid + i*64];
        sqt[tid] = g_sq[b*NN + t*64 + tid];
        __syncthreads();

        #pragma unroll 1
        for (int mm = 0; mm < 64; mm += 2){
            ull k0, k1;
            DIST_KEY(mm,   k0);
            DIST_KEY(mm+1, k1);
            APPEND(k0);
            APPEND(k1);
            if (__any_sync(0xffffffffu, cnt >= CAP-2)) { REBUILD(); }
        }
    }
    REBUILD();
    #undef DIST_KEY
    #undef APPEND
    #undef INSERT
    #undef REBUILD

    #pragma unroll
    for (int j = 0; j < KK; j++)
        g_idx[row*KK + j] = b*NN + (int)(unsigned)(keepc[j*64] & 0xffffffffull);
}

// ---------------------------------------------------------------------------
// a/c GEMM: ac[p][0:64] = A_w h_p + b ; ac[p][64:128] = C_w h_p
// ---------------------------------------------------------------------------
__global__ __launch_bounds__(128) void k_ac(int r, int src)
{
    const float* h = src ? g_hB : g_hA;
    __shared__ __align__(16) float hs[64*HH];   // 16 KB
    int t  = threadIdx.x;
    int p0 = blockIdx.x*64;

    ull wq[32];
    const float* wbase = g_wfT + r*8192;
    #pragma unroll
    for (int j = 0; j < 32; j++){
        float wa = wbase[(2*j  )*128 + t];
        float wb = wbase[(2*j+1)*128 + t];
        wq[j] = pk2(wa, wb);
    }
    float bias = (t < HH) ? g_wb[r*HH + t] : 0.f;

    const float4* src4 = reinterpret_cast<const float4*>(h + p0*HH);
    float4* hs4 = reinterpret_cast<float4*>(hs);
    for (int i = t; i < 1024; i += 128) hs4[i] = src4[i];
    __syncthreads();

    #pragma unroll 2
    for (int p = 0; p < 64; p++){
        const longlong2* hp = reinterpret_cast<const longlong2*>(hs + p*HH);
        ull a0=0, a1=0, a2=0, a3=0;
        #pragma unroll
        for (int q = 0; q < 8; q++){
            longlong2 v = hp[q];
            a0 = fma2(wq[2*q],   (ull)v.x, a0);
            a1 = fma2(wq[2*q+1], (ull)v.y, a1);
        }
        #pragma unroll
        for (int q = 8; q < 16; q++){
            longlong2 v = hp[q];
            a2 = fma2(wq[2*q],   (ull)v.x, a2);
            a3 = fma2(wq[2*q+1], (ull)v.y, a3);
        }
        ull sv = add2(add2(a0,a2), add2(a1,a3));
        g_ac[(p0+p)*128 + t] = bias + lo2(sv) + hi2(sv);
    }
}

// ---------------------------------------------------------------------------
// gather-max + fused row-norm of the output (feeds next round's kNN).
// ---------------------------------------------------------------------------
__global__ void k_gmax(int src)
{
    float* out = src ? g_hA : g_hB;
    __shared__ int idxs[8*KK];
    __shared__ float part[16];
    int tx = threadIdx.x, ty = threadIdx.y;
    int tid = ty*64 + tx;
    int p0 = blockIdx.x*8;
    if (tid < 8*KK) idxs[tid] = g_idx[p0*KK + tid];
    __syncthreads();
    int p = p0 + ty;
    float a = g_ac[p*128 + tx];
    float m = 0.f;                        // relu => candidates clamped at 0
    #pragma unroll
    for (int k = 0; k < KK; k++){
        int nb = idxs[ty*KK + k];
        m = fmaxf(m, a + g_ac[nb*128 + 64 + tx]);
    }
    out[p*HH + tx] = m;

    float ss = m*m;
    #pragma unroll
    for (int off = 16; off; off >>= 1) ss += __shfl_down_sync(0xffffffffu, ss, off);
    if ((tx & 31) == 0) part[tid >> 5] = ss;
    __syncthreads();
    if (tx == 0) g_sq[p] = part[2*ty] + part[2*ty + 1];
}

// ---------------------------------------------------------------------------
// head: u = relu(bn(W_s1 h)); logit = w_s2 . u + b_s2
// ---------------------------------------------------------------------------
__global__ void k_head(int src,
    const float* __restrict__ w1, const float* __restrict__ g1,
    const float* __restrict__ b1,
    const float* __restrict__ w2, const float* __restrict__ b2,
    float* __restrict__ out)
{
    const float* h = src ? g_hB : g_hA;
    __shared__ float w1sT[HH][HH];
    __shared__ __align__(16) float hs[16][HH];
    __shared__ float parts[16][2];
    int tx = threadIdx.x, ty = threadIdx.y;
    int tid = ty*64 + tx;
    int p0 = blockIdx.x*16;

    for (int i = tid; i < HH*HH; i += 1024){ int o = i>>6, hh = i&63; w1sT[hh][o] = w1[i]; }
    hs[ty][tx] = h[(p0+ty)*HH + tx];
    __syncthreads();

    float inv = rsqrtf(1.0f + EPSF);
    float s = g1[tx]*inv, bb = b1[tx];
    float a0=0,a1=0,a2=0,a3=0;
    const float4* hp = reinterpret_cast<const float4*>(hs[ty]);
    #pragma unroll
    for (int q = 0; q < 16; q++){
        float4 v = hp[q];
        int hh = q*4;
        a0 = fmaf(w1sT[hh+0][tx], v.x, a0);
        a1 = fmaf(w1sT[hh+1][tx], v.y, a1);
        a2 = fmaf(w1sT[hh+2][tx], v.z, a2);
        a3 = fmaf(w1sT[hh+3][tx], v.w, a3);
    }
    float u = fmaxf(((a0+a1)+(a2+a3))*s + bb, 0.f);
    float v = u * w2[tx];
    #pragma unroll
    for (int off = 16; off; off >>= 1) v += __shfl_down_sync(0xffffffffu, v, off);
    if ((tx & 31) == 0) parts[ty][tx >> 5] = v;
    __syncthreads();
    if (tx == 0) out[p0 + ty] = parts[ty][0] + parts[ty][1] + b2[0];
}

// ---------------------------------------------------------------------------
extern "C" void kernel_launch(void* const* d_in, const int* in_sizes, int n_in,
                              void* d_out, int out_size)
{
    (void)in_sizes; (void)n_in; (void)out_size;
    const float* x    = (const float*)d_in[0];
    const float* w_t1 = (const float*)d_in[1];
    const float* g_t1 = (const float*)d_in[2];
    const float* b_t1 = (const float*)d_in[3];
    const float* w_t2 = (const float*)d_in[4];
    const float* g_t2 = (const float*)d_in[5];
    const float* b_t2 = (const float*)d_in[6];
    const float* w_nb = (const float*)d_in[7];
    const float* g_nb = (const float*)d_in[8];
    const float* b_nb = (const float*)d_in[9];
    const float* w_s1 = (const float*)d_in[10];
    const float* g_s1 = (const float*)d_in[11];
    const float* b_s1 = (const float*)d_in[12];
    const float* w_s2 = (const float*)d_in[13];
    const float* b_s2 = (const float*)d_in[14];
    float* out = (float*)d_out;

    k_prep<<<64, 256>>>(w_nb, g_nb, b_nb);
    k_input<<<BB*NN/16, dim3(64,16)>>>(x, w_t1, g_t1, b_t1, w_t2, g_t2, b_t2);

    for (int r = 0; r < 2; r++){
        // r==0: read g_hA, write g_hB ; r==1: read g_hB, write g_hA
        k_knn <<<dim3(8,128), 64>>>(r);
        k_ac  <<<BB*NN/64, 128>>>(r, r);
        k_gmax<<<BB*NN/8, dim3(64,8)>>>(r);
    }

    k_head<<<BB*NN/16, dim3(64,16)>>>(0, w_s1, g_s1, b_s1, w_s2, b_s2, out);
}

// round 11
// speedup vs baseline: 1.3371x; 1.0396x over previous
#include <cuda_runtime.h>

#define BB 128
#define NN 512
#define CC 7
#define HH 64
#define KK 16
#define EPSF 1e-5f

typedef unsigned long long ull;

// ---------------- scratch (device globals: allocation-free) ----------------
__device__ __align__(16) float g_hA[BB*NN*HH];      // 16.8 MB
__device__ __align__(16) float g_hB[BB*NN*HH];      // 16.8 MB
__device__ __align__(16) float g_ac[BB*NN*2*HH];    // 33.5 MB  [point][0:64]=a, [64:128]=c
__device__ float g_sq[BB*NN];
__device__ int   g_idx[BB*NN*KK];
__device__ float g_wfT[2*HH*128];                   // folded weights, [r][hh][o] (transposed)
__device__ float g_wb[2*HH];                        // folded bias

// ---------------- packed fp32x2 helpers (Blackwell f32x2 pipe) -------------
__device__ __forceinline__ ull fma2(ull a, ull b, ull c){
    ull d; asm("fma.rn.f32x2 %0, %1, %2, %3;" : "=l"(d) : "l"(a), "l"(b), "l"(c)); return d;
}
__device__ __forceinline__ ull add2(ull a, ull b){
    ull d; asm("add.rn.f32x2 %0, %1, %2;" : "=l"(d) : "l"(a), "l"(b)); return d;
}
__device__ __forceinline__ float lo2(ull a){ return __uint_as_float((unsigned)a); }
__device__ __forceinline__ float hi2(ull a){ return __uint_as_float((unsigned)(a >> 32)); }
__device__ __forceinline__ ull pk2(float lo, float hi){
    ull d; asm("mov.b64 %0, {%1,%2};" : "=l"(d) : "f"(lo), "f"(hi)); return d;
}

// ---------------------------------------------------------------------------
// k_prep: fold BN scale into edgeconv weights, TRANSPOSED layout [r][hh][o]
// ---------------------------------------------------------------------------
__global__ void k_prep(const float* __restrict__ wnb,
                       const float* __restrict__ gnb,
                       const float* __restrict__ bnb)
{
    int i = blockIdx.x*256 + threadIdx.x;
    if (i < 2*HH) g_wb[i] = bnb[i];
    if (i >= 2*HH*128) return;
    int r   = i >> 13;
    int rem = i & 8191;
    int hh  = rem >> 7;
    int o   = rem & 127;
    float inv = rsqrtf(1.0f + EPSF);
    float v;
    if (o < HH){
        float s = gnb[r*HH + o] * inv;
        v = (wnb[(r*HH + o)*128 + hh] - wnb[(r*HH + o)*128 + 64 + hh]) * s;
    } else {
        int oo = o - HH;
        float s = gnb[r*HH + oo] * inv;
        v = wnb[(r*HH + oo)*128 + 64 + hh] * s;
    }
    g_wfT[i] = v;
}

// ---------------------------------------------------------------------------
// k_input: h = relu(bn2(W2 relu(bn1(W1 x)))), fused row-norm (g_sq).
// ---------------------------------------------------------------------------
__global__ void k_input(const float* __restrict__ x,
                        const float* __restrict__ w1, const float* __restrict__ g1,
                        const float* __restrict__ b1,
                        const float* __restrict__ w2, const float* __restrict__ g2,
                        const float* __restrict__ b2)
{
    __shared__ float w1s[HH*CC];
    __shared__ float w2sT[HH][HH];
    __shared__ float xs[16][CC];
    __shared__ __align__(16) float h1s[16][HH];
    __shared__ float part[32];
    int tx = threadIdx.x, ty = threadIdx.y;
    int tid = ty*64 + tx;
    int p0 = blockIdx.x*16;
    int b  = p0 / NN;
    int n0 = p0 % NN;

    for (int i = tid; i < HH*CC; i += 1024) w1s[i] = w1[i];
    for (int i = tid; i < HH*HH; i += 1024) { int o = i>>6, hh = i&63; w2sT[hh][o] = w2[i]; }
    if (tid < 16*CC) { int c = tid/16, i = tid%16; xs[i][c] = x[b*CC*NN + c*NN + n0 + i]; }
    __syncthreads();

    float inv = rsqrtf(1.0f + EPSF);
    float s1 = g1[tx]*inv, bb1 = b1[tx];
    float s2 = g2[tx]*inv, bb2 = b2[tx];

    {
        float acc = 0.f;
        #pragma unroll
        for (int c = 0; c < CC; c++) acc = fmaf(w1s[tx*CC + c], xs[ty][c], acc);
        h1s[ty][tx] = fmaxf(acc*s1 + bb1, 0.f);
    }
    __syncthreads();
    float val;
    {
        float a0=0,a1=0,a2=0,a3=0;
        const float4* hp = reinterpret_cast<const float4*>(h1s[ty]);
        #pragma unroll
        for (int q = 0; q < 16; q++){
            float4 v = hp[q];
            int hh = q*4;
            a0 = fmaf(w2sT[hh+0][tx], v.x, a0);
            a1 = fmaf(w2sT[hh+1][tx], v.y, a1);
            a2 = fmaf(w2sT[hh+2][tx], v.z, a2);
            a3 = fmaf(w2sT[hh+3][tx], v.w, a3);
        }
        val = fmaxf(((a0+a1)+(a2+a3))*s2 + bb2, 0.f);
        g_hA[(p0+ty)*HH + tx] = val;
    }
    float ss = val*val;
    #pragma unroll
    for (int off = 16; off; off >>= 1) ss += __shfl_down_sync(0xffffffffu, ss, off);
    if ((tx & 31) == 0) part[tid >> 5] = ss;
    __syncthreads();
    if (tx == 0) g_sq[p0 + ty] = part[2*ty] + part[2*ty + 1];
}

// ---------------------------------------------------------------------------
// kNN v5: 4-candidate unrolled distance core (8 independent f32x2 chains in
// flight) + branchless filtered append + rare warp-uniform rebuilds.
// Exactness: keys unique (index in low bits), appended in index order, strict
// '<' threshold / evict-max => identical top-16 set and jax.lax.top_k tie
// semantics. CAP=17: sink slot 16; rebuild fires at cnt>=13 so a 4-append
// group can never clobber a real slot with the sink.
// ---------------------------------------------------------------------------
#define CAP 17
__global__ __launch_bounds__(64) void k_knn(int src)
{
    const float* h = src ? g_hB : g_hA;
    __shared__ __align__(16) float tile[64*64];   // 16 KB candidate tile
    __shared__ ull keep[KK][64];                  // 8 KB  top-16 structure
    __shared__ ull buf[CAP][64];                  // 8.5 KB append buffer
    __shared__ float sqt[64];

    int tid = threadIdx.x;
    int b   = blockIdx.y;
    int n   = blockIdx.x*64 + tid;
    int row = b*NN + n;

    ull hq[32];
    {
        const longlong2* hp = reinterpret_cast<const longlong2*>(h + row*HH);
        #pragma unroll
        for (int q = 0; q < 16; q++){
            longlong2 v = hp[q];
            hq[2*q]   = (ull)v.x;
            hq[2*q+1] = (ull)v.y;
        }
    }
    float sqn = g_sq[row];

    ull* keepc = &keep[0][tid];                   // column base, stride 64
    ull* bufc  = &buf[0][tid];
    #pragma unroll
    for (int j = 0; j < KK; j++) keepc[j*64] = ~0ull;
    ull maxA = ~0ull, maxB = ~0ull;               // per-half running max (regs)
    int wsA = 0, wsB = 0;
    ull wkey = ~0ull;                             // stale-but-safe threshold
    int cnt = 0;

    // branchless append: always store (dummy slot when rejected)
    #define APPEND(key) {                                                     \
        int pass = ((key) < wkey);                                            \
        int slot = pass ? cnt : (CAP-1);                                      \
        bufc[slot*64] = (key);                                                \
        cnt += pass;                                                          \
    }

    // evict-max insert into the 16-slot keep structure (split-scan)
    #define INSERT(key) {                                                     \
        ull wk = (maxA > maxB) ? maxA : maxB;                                 \
        if ((key) < wk){                                                      \
            bool ina = (maxA > maxB);                                         \
            int base = ina ? 0 : 8;                                           \
            int ws   = ina ? wsA : wsB;                                       \
            keepc[(base + ws)*64] = (key);                                    \
            ull mx = keepc[base*64]; int ms = 0;                              \
            _Pragma("unroll")                                                 \
            for (int j = 1; j < 8; j++){                                      \
                ull kj = keepc[(base + j)*64];                                \
                if (kj > mx){ mx = kj; ms = j; }                              \
            }                                                                 \
            if (ina){ maxA = mx; wsA = ms; } else { maxB = mx; wsB = ms; }    \
        }                                                                     \
    }

    // warp-uniform rebuild: fold buffered keys into keep, tighten threshold
    #define REBUILD() {                                                       \
        int vm = (int)__reduce_max_sync(0xffffffffu, (unsigned)cnt);          \
        for (int j = 0; j < vm; j++){                                         \
            ull kk = (j < cnt) ? bufc[j*64] : ~0ull;                          \
            INSERT(kk);                                                       \
        }                                                                     \
        wkey = (maxA > maxB) ? maxA : maxB;                                   \
        cnt = 0;                                                              \
    }

    for (int t = 0; t < 8; t++){
        __syncthreads();
        const float4* s4 = reinterpret_cast<const float4*>(h + (b*NN + t*64)*HH);
        float4* t4 = reinterpret_cast<float4*>(tile);
        #pragma unroll
        for (int i = 0; i < 16; i++) t4[tid + i*64] = s4[tid + i*64];
        sqt[tid] = g_sq[b*NN + t*64 + tid];
        __syncthreads();

        #pragma unroll 1
        for (int mm = 0; mm < 64; mm += 4){
            // 4-candidate distance core: 8 independent fma2 chains
            const longlong2* tp = reinterpret_cast<const longlong2*>(tile + mm*64);
            ull a0=0,b0=0, a1=0,b1=0, a2=0,b2=0, a3=0,b3=0;
            #pragma unroll
            for (int q = 0; q < 16; q++){
                longlong2 v0 = tp[q];
                longlong2 v1 = tp[q+16];
                longlong2 v2 = tp[q+32];
                longlong2 v3 = tp[q+48];
                ull hx = hq[2*q], hy = hq[2*q+1];
                a0 = fma2(hx, (ull)v0.x, a0);  b0 = fma2(hy, (ull)v0.y, b0);
                a1 = fma2(hx, (ull)v1.x, a1);  b1 = fma2(hy, (ull)v1.y, b1);
                a2 = fma2(hx, (ull)v2.x, a2);  b2 = fma2(hy, (ull)v2.y, b2);
                a3 = fma2(hx, (ull)v3.x, a3);  b3 = fma2(hy, (ull)v3.y, b3);
            }
            ull s0 = add2(a0,b0), s1 = add2(a1,b1);
            ull s2 = add2(a2,b2), s3 = add2(a3,b3);
            float d0 = fmaxf(sqn + sqt[mm  ] - 2.0f*(lo2(s0)+hi2(s0)), 0.f);
            float d1 = fmaxf(sqn + sqt[mm+1] - 2.0f*(lo2(s1)+hi2(s1)), 0.f);
            float d2 = fmaxf(sqn + sqt[mm+2] - 2.0f*(lo2(s2)+hi2(s2)), 0.f);
            float d3 = fmaxf(sqn + sqt[mm+3] - 2.0f*(lo2(s3)+hi2(s3)), 0.f);
            ull k0 = ((ull)__float_as_uint(d0) << 32) | (unsigned)(t*64 + mm);
            ull k1 = ((ull)__float_as_uint(d1) << 32) | (unsigned)(t*64 + mm + 1);
            ull k2 = ((ull)__float_as_uint(d2) << 32) | (unsigned)(t*64 + mm + 2);
            ull k3 = ((ull)__float_as_uint(d3) << 32) | (unsigned)(t*64 + mm + 3);
            APPEND(k0);
            APPEND(k1);
            APPEND(k2);
            APPEND(k3);
            if (__any_sync(0xffffffffu, cnt >= CAP-4)) { REBUILD(); }
        }
    }
    REBUILD();
    #undef APPEND
    #undef INSERT
    #undef REBUILD

    #pragma unroll
    for (int j = 0; j < KK; j++)
        g_idx[row*KK + j] = b*NN + (int)(unsigned)(keepc[j*64] & 0xffffffffull);
}

// ---------------------------------------------------------------------------
// a/c GEMM: ac[p][0:64] = A_w h_p + b ; ac[p][64:128] = C_w h_p
// 2 points per iteration: two independent 4-chain FMA clusters in flight.
// Per-point numerics identical to previous version.
// ---------------------------------------------------------------------------
__global__ __launch_bounds__(128) void k_ac(int r, int src)
{
    const float* h = src ? g_hB : g_hA;
    __shared__ __align__(16) float hs[64*HH];   // 16 KB
    int t  = threadIdx.x;
    int p0 = blockIdx.x*64;

    ull wq[32];
    const float* wbase = g_wfT + r*8192;
    #pragma unroll
    for (int j = 0; j < 32; j++){
        float wa = wbase[(2*j  )*128 + t];
        float wb = wbase[(2*j+1)*128 + t];
        wq[j] = pk2(wa, wb);
    }
    float bias = (t < HH) ? g_wb[r*HH + t] : 0.f;

    const float4* src4 = reinterpret_cast<const float4*>(h + p0*HH);
    float4* hs4 = reinterpret_cast<float4*>(hs);
    for (int i = t; i < 1024; i += 128) hs4[i] = src4[i];
    __syncthreads();

    #pragma unroll 1
    for (int p = 0; p < 64; p += 2){
        const longlong2* hp = reinterpret_cast<const longlong2*>(hs + p*HH);
        ull a0=0, a1=0, a2=0, a3=0;
        ull c0=0, c1=0, c2=0, c3=0;
        #pragma unroll
        for (int q = 0; q < 8; q++){
            longlong2 v = hp[q];
            longlong2 w = hp[q+16];
            a0 = fma2(wq[2*q],   (ull)v.x, a0);
            a1 = fma2(wq[2*q+1], (ull)v.y, a1);
            c0 = fma2(wq[2*q],   (ull)w.x, c0);
            c1 = fma2(wq[2*q+1], (ull)w.y, c1);
        }
        #pragma unroll
        for (int q = 8; q < 16; q++){
            longlong2 v = hp[q];
            longlong2 w = hp[q+16];
            a2 = fma2(wq[2*q],   (ull)v.x, a2);
            a3 = fma2(wq[2*q+1], (ull)v.y, a3);
            c2 = fma2(wq[2*q],   (ull)w.x, c2);
            c3 = fma2(wq[2*q+1], (ull)w.y, c3);
        }
        ull sv = add2(add2(a0,a2), add2(a1,a3));
        ull sw = add2(add2(c0,c2), add2(c1,c3));
        g_ac[(p0+p  )*128 + t] = bias + lo2(sv) + hi2(sv);
        g_ac[(p0+p+1)*128 + t] = bias + lo2(sw) + hi2(sw);
    }
}

// ---------------------------------------------------------------------------
// gather-max + fused row-norm of the output (feeds next round's kNN).
// ---------------------------------------------------------------------------
__global__ void k_gmax(int src)
{
    float* out = src ? g_hA : g_hB;
    __shared__ int idxs[8*KK];
    __shared__ float part[16];
    int tx = threadIdx.x, ty = threadIdx.y;
    int tid = ty*64 + tx;
    int p0 = blockIdx.x*8;
    if (tid < 8*KK) idxs[tid] = g_idx[p0*KK + tid];
    __syncthreads();
    int p = p0 + ty;
    float a = g_ac[p*128 + tx];
    float m = 0.f;                        // relu => candidates clamped at 0
    #pragma unroll
    for (int k = 0; k < KK; k++){
        int nb = idxs[ty*KK + k];
        m = fmaxf(m, a + g_ac[nb*128 + 64 + tx]);
    }
    out[p*HH + tx] = m;

    float ss = m*m;
    #pragma unroll
    for (int off = 16; off; off >>= 1) ss += __shfl_down_sync(0xffffffffu, ss, off);
    if ((tx & 31) == 0) part[tid >> 5] = ss;
    __syncthreads();
    if (tx == 0) g_sq[p] = part[2*ty] + part[2*ty + 1];
}

// ---------------------------------------------------------------------------
// head: u = relu(bn(W_s1 h)); logit = w_s2 . u + b_s2
// ---------------------------------------------------------------------------
__global__ void k_head(int src,
    const float* __restrict__ w1, const float* __restrict__ g1,
    const float* __restrict__ b1,
    const float* __restrict__ w2, const float* __restrict__ b2,
    float* __restrict__ out)
{
    const float* h = src ? g_hB : g_hA;
    __shared__ float w1sT[HH][HH];
    __shared__ __align__(16) float hs[16][HH];
    __shared__ float parts[16][2];
    int tx = threadIdx.x, ty = threadIdx.y;
    int tid = ty*64 + tx;
    int p0 = blockIdx.x*16;

    for (int i = tid; i < HH*HH; i += 1024){ int o = i>>6, hh = i&63; w1sT[hh][o] = w1[i]; }
    hs[ty][tx] = h[(p0+ty)*HH + tx];
    __syncthreads();

    float inv = rsqrtf(1.0f + EPSF);
    float s = g1[tx]*inv, bb = b1[tx];
    float a0=0,a1=0,a2=0,a3=0;
    const float4* hp = reinterpret_cast<const float4*>(hs[ty]);
    #pragma unroll
    for (int q = 0; q < 16; q++){
        float4 v = hp[q];
        int hh = q*4;
        a0 = fmaf(w1sT[hh+0][tx], v.x, a0);
        a1 = fmaf(w1sT[hh+1][tx], v.y, a1);
        a2 = fmaf(w1sT[hh+2][tx], v.z, a2);
        a3 = fmaf(w1sT[hh+3][tx], v.w, a3);
    }
    float u = fmaxf(((a0+a1)+(a2+a3))*s + bb, 0.f);
    float v = u * w2[tx];
    #pragma unroll
    for (int off = 16; off; off >>= 1) v += __shfl_down_sync(0xffffffffu, v, off);
    if ((tx & 31) == 0) parts[ty][tx >> 5] = v;
    __syncthreads();
    if (tx == 0) out[p0 + ty] = parts[ty][0] + parts[ty][1] + b2[0];
}

// ---------------------------------------------------------------------------
extern "C" void kernel_launch(void* const* d_in, const int* in_sizes, int n_in,
                              void* d_out, int out_size)
{
    (void)in_sizes; (void)n_in; (void)out_size;
    const float* x    = (const float*)d_in[0];
    const float* w_t1 = (const float*)d_in[1];
    const float* g_t1 = (const float*)d_in[2];
    const float* b_t1 = (const float*)d_in[3];
    const float* w_t2 = (const float*)d_in[4];
    const float* g_t2 = (const float*)d_in[5];
    const float* b_t2 = (const float*)d_in[6];
    const float* w_nb = (const float*)d_in[7];
    const float* g_nb = (const float*)d_in[8];
    const float* b_nb = (const float*)d_in[9];
    const float* w_s1 = (const float*)d_in[10];
    const float* g_s1 = (const float*)d_in[11];
    const float* b_s1 = (const float*)d_in[12];
    const float* w_s2 = (const float*)d_in[13];
    const float* b_s2 = (const float*)d_in[14];
    float* out = (float*)d_out;

    k_prep<<<64, 256>>>(w_nb, g_nb, b_nb);
    k_input<<<BB*NN/16, dim3(64,16)>>>(x, w_t1, g_t1, b_t1, w_t2, g_t2, b_t2);

    for (int r = 0; r < 2; r++){
        // r==0: read g_hA, write g_hB ; r==1: read g_hB, write g_hA
        k_knn <<<dim3(8,128), 64>>>(r);
        k_ac  <<<BB*NN/64, 128>>>(r, r);
        k_gmax<<<BB*NN/8, dim3(64,8)>>>(r);
    }

    k_head<<<BB*NN/16, dim3(64,16)>>>(0, w_s1, g_s1, b_s1, w_s2, b_s2, out);
}